// round 3
// baseline (speedup 1.0000x reference)
#include <cuda_runtime.h>
#include <cuda_bf16.h>
#include <cstdint>

// ---------------------------------------------------------------------------
// Problem constants
// ---------------------------------------------------------------------------
#define BB   32      // batch
#define TT   448     // time
#define DD   768     // input dim
#define HH   256     // hidden
#define G4   1024    // 4*H
#define NTAGS 2

typedef unsigned long long u64;

// ---------------------------------------------------------------------------
// Scratch (device globals; allocation-free)
// ---------------------------------------------------------------------------
__device__ float g_gx[2u * TT * BB * G4];          // [dir][t][b][4H]  117 MB
__device__ float g_hs[2u * BB * TT * HH];          // [dir][b][t][h]   29 MB
__device__ float g_hbuf[2 * 2 * BB * HH];          // [phase][dir][b][h]
__device__ float g_logits[BB * TT * NTAGS];
__device__ float g_kdpart[1024];
__device__ unsigned int g_bar;

// ---------------------------------------------------------------------------
// f32x2 packed helpers (Blackwell FFMA2 path — PTX only)
// ---------------------------------------------------------------------------
__device__ __forceinline__ u64 pack2(float lo, float hi) {
    u64 r;
    asm("mov.b64 %0, {%1, %2};" : "=l"(r) : "f"(lo), "f"(hi));
    return r;
}
__device__ __forceinline__ float2 unpack2(u64 v) {
    float2 f;
    asm("mov.b64 {%0, %1}, %2;" : "=f"(f.x), "=f"(f.y) : "l"(v));
    return f;
}
__device__ __forceinline__ void fma2(u64 &acc, u64 a, u64 b) {
    asm("fma.rn.f32x2 %0, %1, %2, %3;" : "=l"(acc) : "l"(a), "l"(b), "l"(acc));
}

// ---------------------------------------------------------------------------
// init: reset barrier + zero h state (phase 0)
// ---------------------------------------------------------------------------
__global__ void init_kernel() {
    if (threadIdx.x == 0) g_bar = 0u;
    for (int i = threadIdx.x; i < 2 * BB * HH; i += 256) g_hbuf[i] = 0.f;
}

// ---------------------------------------------------------------------------
// Input GEMM: gx[dir][t][b][row] = x[b,t,:] . Wih[dir][row,:] + bih + bhh
// 128x128 tile, BK=16, 256 threads, 8x8 micro-tile with fma.rn.f32x2
// ---------------------------------------------------------------------------
#define GM 128
#define GN 128
#define GK 16

__global__ void __launch_bounds__(256) gemm_kernel(
    const float* __restrict__ x,
    const float* __restrict__ Wf, const float* __restrict__ Wb,
    const float* __restrict__ bihf, const float* __restrict__ bhhf,
    const float* __restrict__ bihb, const float* __restrict__ bhhb)
{
    const int dir = blockIdx.z;
    const float* __restrict__ W  = dir ? Wb   : Wf;
    const float* __restrict__ bi = dir ? bihb : bihf;
    const float* __restrict__ bh = dir ? bhhb : bhhf;

    __shared__ __align__(16) float As[GK][GM + 4];
    __shared__ __align__(16) float Bs[GK][GN + 4];

    const int tid = threadIdx.x;
    const int m0 = blockIdx.x * GM;
    const int n0 = blockIdx.y * GN;
    const int tx = tid & 15, ty = tid >> 4;

    u64 acc[8][4];
#pragma unroll
    for (int i = 0; i < 8; i++)
#pragma unroll
        for (int j = 0; j < 4; j++) acc[i][j] = 0ull;

    for (int kt = 0; kt < DD; kt += GK) {
#pragma unroll
        for (int q = 0; q < 2; q++) {
            int fi = tid + q * 256;
            int r  = fi >> 2, c4 = fi & 3;
            float4 av = *(const float4*)(x + (size_t)(m0 + r) * DD + kt + c4 * 4);
            float4 bv = *(const float4*)(W + (size_t)(n0 + r) * DD + kt + c4 * 4);
            As[c4 * 4 + 0][r] = av.x; As[c4 * 4 + 1][r] = av.y;
            As[c4 * 4 + 2][r] = av.z; As[c4 * 4 + 3][r] = av.w;
            Bs[c4 * 4 + 0][r] = bv.x; Bs[c4 * 4 + 1][r] = bv.y;
            Bs[c4 * 4 + 2][r] = bv.z; Bs[c4 * 4 + 3][r] = bv.w;
        }
        __syncthreads();
#pragma unroll
        for (int k = 0; k < GK; k++) {
            float4 a0 = *(const float4*)&As[k][ty * 8];
            float4 a1 = *(const float4*)&As[k][ty * 8 + 4];
            float4 b0 = *(const float4*)&Bs[k][tx * 8];
            float4 b1 = *(const float4*)&Bs[k][tx * 8 + 4];
            u64 bb2[4] = { pack2(b0.x, b0.y), pack2(b0.z, b0.w),
                           pack2(b1.x, b1.y), pack2(b1.z, b1.w) };
            float aa[8] = { a0.x, a0.y, a0.z, a0.w, a1.x, a1.y, a1.z, a1.w };
#pragma unroll
            for (int mi = 0; mi < 8; mi++) {
                u64 a2 = pack2(aa[mi], aa[mi]);
#pragma unroll
                for (int nj = 0; nj < 4; nj++) fma2(acc[mi][nj], a2, bb2[nj]);
            }
        }
        __syncthreads();
    }

#pragma unroll
    for (int mi = 0; mi < 8; mi++) {
        int m = m0 + ty * 8 + mi;
        int bidx = m / TT, t = m % TT;
        float* dst = g_gx + (((size_t)dir * TT + t) * BB + bidx) * G4 + n0 + tx * 8;
#pragma unroll
        for (int nj = 0; nj < 4; nj++) {
            float2 v = unpack2(acc[mi][nj]);
            int n = n0 + tx * 8 + nj * 2;
            v.x += bi[n]     + bh[n];
            v.y += bi[n + 1] + bh[n + 1];
            ((float2*)dst)[nj] = v;
        }
    }
}

// ---------------------------------------------------------------------------
// KD loss partials: sum((s - t)^2), 1024 deterministic block partials
// ---------------------------------------------------------------------------
__global__ void __launch_bounds__(256) kd_kernel(const float* __restrict__ s,
                                                 const float* __restrict__ t)
{
    __shared__ float red[256];
    const size_t N4 = (size_t)3 * BB * TT * DD / 4;   // 8,257,536
    const float4* s4 = (const float4*)s;
    const float4* t4 = (const float4*)t;
    float acc = 0.f;
    for (size_t i = (size_t)blockIdx.x * 256 + threadIdx.x; i < N4; i += 262144) {
        float4 a = __ldg(s4 + i);
        float4 b = __ldg(t4 + i);
        float dx = a.x - b.x, dy = a.y - b.y, dz = a.z - b.z, dw = a.w - b.w;
        acc += dx * dx + dy * dy + dz * dz + dw * dw;
    }
    red[threadIdx.x] = acc;
    __syncthreads();
    for (int o = 128; o; o >>= 1) {
        if (threadIdx.x < o) red[threadIdx.x] += red[threadIdx.x + o];
        __syncthreads();
    }
    if (threadIdx.x == 0) g_kdpart[blockIdx.x] = red[0];
}

// ---------------------------------------------------------------------------
// Persistent BiLSTM recurrence.
// 128 blocks = 2 dir x 32 hid-groups(8 units) x 2 batch-groups(16 batches).
// 256 threads: warp w = k-slice (32 k each), lane rl = gate-row (4 gates x 8).
// W_hh slice kept in registers; h staged via SMEM broadcast; c in registers.
// Grid barrier per step via monotonically increasing counter.
// ---------------------------------------------------------------------------
__device__ __forceinline__ float sigmoid_f(float x) {
    return 1.f / (1.f + __expf(-x));
}
__device__ __forceinline__ float tanh_f(float x) {
    x = fminf(15.f, fmaxf(-15.f, x));
    float e = __expf(2.f * x);
    return (e - 1.f) / (e + 1.f);
}

__global__ void __launch_bounds__(256, 1) recur_kernel(
    const float* __restrict__ Whhf, const float* __restrict__ Whhb)
{
    const int tid = threadIdx.x;
    const int w   = tid >> 5;        // 0..7  k-slice
    const int rl  = tid & 31;        // 0..31 local gate-row
    const int blk = blockIdx.x;
    const int dir = blk >> 6;
    const int hg  = (blk & 63) >> 1;
    const int bg  = blk & 1;
    const int hidbase = hg * 8;
    const int bbase   = bg * 16;
    const int R = ((rl >> 3) << 8) + hidbase + (rl & 7);   // global gate row

    const float* __restrict__ Whh = dir ? Whhb : Whhf;

    // Load this thread's 32 weights into registers (packed as 16 f32x2)
    u64 Wreg[16];
    {
        const float4* wp = (const float4*)(Whh + (size_t)R * HH + w * 32);
#pragma unroll
        for (int i = 0; i < 8; i++) {
            float4 v = wp[i];
            Wreg[2 * i]     = pack2(v.x, v.y);
            Wreg[2 * i + 1] = pack2(v.z, v.w);
        }
    }

    __shared__ __align__(16) float h_s[16 * HH];       // 16 KB
    __shared__ float part_s[8 * 16 * 32];              // [w][b][rl] 16 KB
    __shared__ float gate_s[16 * 32];                  // [b][rl]     2 KB

    float c_state = 0.f;
    const int bl = tid >> 3;   // cell-update mapping (tid<128): batch-local
    const int jj = tid & 7;    //                               hid-local

    for (int s = 0; s < TT; s++) {
        const int t = dir ? (TT - 1 - s) : s;

        // ---- stage h (L2-coherent reads) ----
        {
            const float4* src = (const float4*)(g_hbuf +
                ((size_t)((s & 1) * 2 + dir) * BB + bbase) * HH);
            float4* dst4 = (float4*)h_s;
#pragma unroll
            for (int q = 0; q < 4; q++)
                dst4[tid + q * 256] = __ldcg(src + tid + q * 256);
        }
        __syncthreads();

        // ---- prefetch gx for the two outputs this thread will reduce ----
        float gx0, gx1;
        {
            const float* gxp = g_gx + (((size_t)dir * TT + t) * BB + bbase) * G4;
            gx0 = __ldg(gxp + (size_t)w * G4 + R);        // output (b=w,    rl)
            gx1 = __ldg(gxp + (size_t)(8 + w) * G4 + R);  // output (b=8+w,  rl)
        }

        // ---- partial dot products over this warp's k-slice ----
#pragma unroll 4
        for (int b = 0; b < 16; b++) {
            const u64* h2 = (const u64*)(h_s + b * HH + w * 32);
            u64 acc = 0ull;
#pragma unroll
            for (int i = 0; i < 16; i++) fma2(acc, Wreg[i], h2[i]);
            float2 f = unpack2(acc);
            part_s[w * 512 + b * 32 + rl] = f.x + f.y;
        }
        __syncthreads();

        // ---- cross-slice reduction + gx + store gates ----
        {
            float s0 = gx0, s1 = gx1;
#pragma unroll
            for (int q = 0; q < 8; q++) {
                s0 += part_s[q * 512 + w * 32 + rl];
                s1 += part_s[q * 512 + (8 + w) * 32 + rl];
            }
            gate_s[w * 32 + rl]       = s0;
            gate_s[(8 + w) * 32 + rl] = s1;
        }
        __syncthreads();

        // ---- cell update (128 threads own the 16x8 cell states) ----
        if (tid < 128) {
            float gi = gate_s[bl * 32 + jj];
            float gf = gate_s[bl * 32 + 8 + jj];
            float gg = gate_s[bl * 32 + 16 + jj];
            float go = gate_s[bl * 32 + 24 + jj];
            float si = sigmoid_f(gi);
            float sf = sigmoid_f(gf);
            float so = sigmoid_f(go);
            c_state = sf * c_state + si * tanh_f(gg);
            float h = so * tanh_f(c_state);
            int bglob = bbase + bl;
            int hglob = hidbase + jj;
            __stcg(g_hbuf + ((size_t)(((s + 1) & 1) * 2 + dir) * BB + bglob) * HH + hglob, h);
            g_hs[(((size_t)dir * BB + bglob) * TT + t) * HH + hglob] = h;
            __threadfence();
        }
        __syncthreads();

        // ---- grid barrier ----
        if (tid == 0) {
            __threadfence();
            atomicAdd(&g_bar, 1u);
            unsigned target = 128u * (unsigned)(s + 1);
            while (*(volatile unsigned*)&g_bar < target) __nanosleep(40);
            __threadfence();
        }
        __syncthreads();
    }
}

// ---------------------------------------------------------------------------
// Logits: one warp per (b,t) row; 2 dots of length 512
// ---------------------------------------------------------------------------
__global__ void __launch_bounds__(256) logits_kernel(
    const float* __restrict__ Wcls, const float* __restrict__ bcls)
{
    __shared__ __align__(16) float Ws[2 * 512];
    const int tid = threadIdx.x;
    for (int i = tid; i < 1024; i += 256) Ws[i] = Wcls[i];
    __syncthreads();

    const int warp = tid >> 5, lane = tid & 31;
    const int row = blockIdx.x * 8 + warp;            // 0..14335
    const int b = row / TT, t = row % TT;

    const float4* hf  = (const float4*)(g_hs + ((size_t)b * TT + t) * HH);
    const float4* hb  = (const float4*)(g_hs + (((size_t)BB + b) * TT + t) * HH);
    const float4* W0  = (const float4*)Ws;            // row 0, 512 floats
    const float4* W1  = (const float4*)(Ws + 512);    // row 1

    float a0 = 0.f, a1 = 0.f;
#pragma unroll
    for (int q = 0; q < 2; q++) {
        int u = lane + q * 32;
        float4 v  = hf[u];
        float4 w0 = W0[u];
        float4 w1 = W1[u];
        a0 += v.x * w0.x + v.y * w0.y + v.z * w0.z + v.w * w0.w;
        a1 += v.x * w1.x + v.y * w1.y + v.z * w1.z + v.w * w1.w;
    }
#pragma unroll
    for (int q = 0; q < 2; q++) {
        int u = lane + q * 32;
        float4 v  = hb[u];
        float4 w0 = W0[64 + u];
        float4 w1 = W1[64 + u];
        a0 += v.x * w0.x + v.y * w0.y + v.z * w0.z + v.w * w0.w;
        a1 += v.x * w1.x + v.y * w1.y + v.z * w1.z + v.w * w1.w;
    }
#pragma unroll
    for (int o = 16; o; o >>= 1) {
        a0 += __shfl_down_sync(0xffffffffu, a0, o);
        a1 += __shfl_down_sync(0xffffffffu, a1, o);
    }
    if (lane == 0) {
        g_logits[row * 2]     = a0 + bcls[0];
        g_logits[row * 2 + 1] = a1 + bcls[1];
    }
}

// ---------------------------------------------------------------------------
// CRF forward + numerator + final loss (one warp, one thread per batch)
// ---------------------------------------------------------------------------
__device__ __forceinline__ float lse2(float a, float b) {
    float m = fmaxf(a, b);
    return m + log1pf(__expf(-fabsf(a - b)));
}

__global__ void crf_kernel(const float* __restrict__ cst,
                           const float* __restrict__ cen,
                           const float* __restrict__ ctr,
                           const int* __restrict__ labels,
                           const int* __restrict__ mask,
                           float* __restrict__ out)
{
    const int b = threadIdx.x;   // 32 threads
    const float tr00 = ctr[0], tr01 = ctr[1], tr10 = ctr[2], tr11 = ctr[3];
    const float* em = g_logits + (size_t)b * TT * 2;
    const int* lab = labels + (size_t)b * TT;
    const int* msk = mask   + (size_t)b * TT;

    float e0 = em[0], e1 = em[1];
    float a0 = cst[0] + e0, a1 = cst[1] + e1;

    int tag_prev = lab[0]; if (tag_prev == -100) tag_prev = 0;
    float num = cst[tag_prev] + (tag_prev ? e1 : e0);
    int cnt = 1;

    for (int t = 1; t < TT; t++) {
        int mraw = msk[t];
        float mt = (mraw != 0) ? 1.f : 0.f;
        float em0 = em[t * 2], em1 = em[t * 2 + 1];
        int tag = lab[t]; if (tag == -100) tag = 0;

        float trs = tag ? (tag_prev ? tr11 : tr01) : (tag_prev ? tr10 : tr00);
        float ems = tag ? em1 : em0;
        num += mt * (trs + ems);
        tag_prev = tag;
        cnt += (mraw != 0);

        float n0 = em0 + lse2(a0 + tr00, a1 + tr10);
        float n1 = em1 + lse2(a0 + tr01, a1 + tr11);
        if (mraw != 0) { a0 = n0; a1 = n1; }
    }
    int lt = lab[cnt - 1]; if (lt == -100) lt = 0;
    num += cen[lt];

    float logZ = lse2(a0 + cen[0], a1 + cen[1]);
    float v = num - logZ;

    // deterministic KD partial sum: lane b sums its fixed 32 slots
    float kdp = 0.f;
#pragma unroll
    for (int i = 0; i < 32; i++) kdp += g_kdpart[b * 32 + i];

#pragma unroll
    for (int o = 16; o; o >>= 1) {
        v   += __shfl_down_sync(0xffffffffu, v, o);
        kdp += __shfl_down_sync(0xffffffffu, kdp, o);
    }
    if (b == 0) {
        float span = -v / (float)BB;
        float kd = kdp / ((float)3 * BB * TT * DD);
        out[0] = 0.5f * span + 0.5f * kd;
    }
}

// ---------------------------------------------------------------------------
// Launch
// ---------------------------------------------------------------------------
extern "C" void kernel_launch(void* const* d_in, const int* in_sizes, int n_in,
                              void* d_out, int out_size)
{
    const float* top  = (const float*)d_in[0];
    const float* sfe  = (const float*)d_in[1];
    const float* tfe  = (const float*)d_in[2];
    const float* Wihf = (const float*)d_in[3];
    const float* Whhf = (const float*)d_in[4];
    const float* bihf = (const float*)d_in[5];
    const float* bhhf = (const float*)d_in[6];
    const float* Wihb = (const float*)d_in[7];
    const float* Whhb = (const float*)d_in[8];
    const float* bihb = (const float*)d_in[9];
    const float* bhhb = (const float*)d_in[10];
    const float* Wcls = (const float*)d_in[11];
    const float* bcls = (const float*)d_in[12];
    const float* cst  = (const float*)d_in[13];
    const float* cen  = (const float*)d_in[14];
    const float* ctr  = (const float*)d_in[15];
    const int*   lab  = (const int*)d_in[16];
    const int*   msk  = (const int*)d_in[17];
    float* out = (float*)d_out;

    init_kernel<<<1, 256>>>();

    dim3 gg(14336 / GM, G4 / GN, 2);                 // 112 x 8 x 2
    gemm_kernel<<<gg, 256>>>(top, Wihf, Wihb, bihf, bhhf, bihb, bhhb);

    kd_kernel<<<1024, 256>>>(sfe, tfe);

    recur_kernel<<<128, 256>>>(Whhf, Whhb);

    logits_kernel<<<(BB * TT) / 8, 256>>>(Wcls, bcls);

    crf_kernel<<<1, 32>>>(cst, cen, ctr, lab, msk, out);
}

// round 10
// speedup vs baseline: 1.6330x; 1.6330x over previous
#include <cuda_runtime.h>
#include <cuda_bf16.h>
#include <cstdint>

// ---------------------------------------------------------------------------
// Problem constants
// ---------------------------------------------------------------------------
#define BB   32      // batch
#define TT   448     // time
#define DD   768     // input dim
#define HH   256     // hidden
#define G4   1024    // 4*H
#define NTAGS 2

typedef unsigned long long u64;

// ---------------------------------------------------------------------------
// Scratch (device globals; allocation-free)
// ---------------------------------------------------------------------------
__device__ float g_gx[2u * TT * BB * G4];          // [dir][t][b][4H]  117 MB
__device__ float g_hs[2u * BB * TT * HH];          // [dir][b][t][h]   29 MB
__device__ float g_hbuf[2 * 2 * BB * HH];          // [phase][dir][b][h]
__device__ float g_logits[BB * TT * NTAGS];
__device__ float g_kdpart[1024];
__device__ unsigned int g_barg[128];               // 4 group barriers, padded
__device__ __nv_bfloat16 g_xb[(size_t)BB * TT * DD];      // bf16 x     22 MB
__device__ __nv_bfloat16 g_wb[(size_t)2 * G4 * DD];       // bf16 W_ih   3 MB

// ---------------------------------------------------------------------------
// f32x2 packed helpers (recurrence path)
// ---------------------------------------------------------------------------
__device__ __forceinline__ u64 pack2(float lo, float hi) {
    u64 r; asm("mov.b64 %0, {%1, %2};" : "=l"(r) : "f"(lo), "f"(hi)); return r;
}
__device__ __forceinline__ float2 unpack2(u64 v) {
    float2 f; asm("mov.b64 {%0, %1}, %2;" : "=f"(f.x), "=f"(f.y) : "l"(v)); return f;
}
__device__ __forceinline__ void fma2(u64 &acc, u64 a, u64 b) {
    asm("fma.rn.f32x2 %0, %1, %2, %3;" : "=l"(acc) : "l"(a), "l"(b), "l"(acc));
}

// ---------------------------------------------------------------------------
// mma.sync / ldmatrix / cp.async helpers (plain sm_80+ PTX, safe on sm_103)
// ---------------------------------------------------------------------------
__device__ __forceinline__ uint32_t smem_u32(const void* p) {
    uint32_t a;
    asm("{ .reg .u64 t; cvta.to.shared.u64 t, %1; cvt.u32.u64 %0, t; }" : "=r"(a) : "l"(p));
    return a;
}
#define CP_ASYNC16(dst, src) \
    asm volatile("cp.async.cg.shared.global [%0], [%1], 16;" :: "r"(dst), "l"(src))
#define CP_COMMIT() asm volatile("cp.async.commit_group;")
#define CP_WAIT(n)  asm volatile("cp.async.wait_group %0;" :: "n"(n))

__device__ __forceinline__ void ldsm_x4(uint32_t &r0, uint32_t &r1, uint32_t &r2, uint32_t &r3,
                                        uint32_t addr) {
    asm volatile("ldmatrix.sync.aligned.m8n8.x4.shared.b16 {%0,%1,%2,%3}, [%4];"
                 : "=r"(r0), "=r"(r1), "=r"(r2), "=r"(r3) : "r"(addr));
}
__device__ __forceinline__ void mma_16816(float* d, const uint32_t* a, uint32_t b0, uint32_t b1) {
    asm volatile("mma.sync.aligned.m16n8k16.row.col.f32.bf16.bf16.f32 "
                 "{%0,%1,%2,%3}, {%4,%5,%6,%7}, {%8,%9}, {%0,%1,%2,%3};"
                 : "+f"(d[0]), "+f"(d[1]), "+f"(d[2]), "+f"(d[3])
                 : "r"(a[0]), "r"(a[1]), "r"(a[2]), "r"(a[3]), "r"(b0), "r"(b1));
}
__device__ __forceinline__ uint32_t sw128(uint32_t off) {
    return off ^ ((off >> 3) & 0x70u);
}

// ---------------------------------------------------------------------------
// init: reset barriers + zero h state (phase 0)
// ---------------------------------------------------------------------------
__global__ void init_kernel() {
    if (threadIdx.x < 128) g_barg[threadIdx.x] = 0u;
    for (int i = threadIdx.x; i < 2 * BB * HH; i += 256) g_hbuf[i] = 0.f;
}

// ---------------------------------------------------------------------------
// fp32 -> bf16 conversion of x and both W_ih matrices
// ---------------------------------------------------------------------------
#define NX4  ((size_t)BB * TT * DD / 4)     // 2,752,512
#define NW4  ((size_t)G4 * DD / 4)          //   196,608
__global__ void __launch_bounds__(256) cvt_kernel(const float* __restrict__ x,
                                                  const float* __restrict__ Wf,
                                                  const float* __restrict__ Wb)
{
    const size_t total = NX4 + 2 * NW4;
    const size_t stride = (size_t)gridDim.x * 256;
    for (size_t i = (size_t)blockIdx.x * 256 + threadIdx.x; i < total; i += stride) {
        const float4* src; uint2* dst; size_t j;
        if (i < NX4)            { src = (const float4*)x;  j = i;             dst = (uint2*)g_xb; }
        else if (i < NX4 + NW4) { src = (const float4*)Wf; j = i - NX4;       dst = (uint2*)g_wb; }
        else                    { src = (const float4*)Wb; j = i - NX4 - NW4; dst = (uint2*)g_wb + NW4; }
        float4 v = __ldg(src + j);
        __nv_bfloat162 p0 = __floats2bfloat162_rn(v.x, v.y);
        __nv_bfloat162 p1 = __floats2bfloat162_rn(v.z, v.w);
        dst[j] = make_uint2(*(uint32_t*)&p0, *(uint32_t*)&p1);
    }
}

// ---------------------------------------------------------------------------
// bf16 HMMA input GEMM: gx[dir][t][b][n] = x[b,t,:] . Wih[dir][n,:] + biases
// Block: 128x128 tile, 8 warps (warp tile 32x64), K in 12 chunks of 64,
// cp.async double-buffered SW128-swizzled SMEM, ldmatrix fragment loads.
// ---------------------------------------------------------------------------
#define SM_BIAS  0           // 128 floats (512 B)
#define SM_A0    1024
#define SM_B0    (SM_A0 + 16384)
#define SM_A1    (SM_B0 + 16384)
#define SM_B1    (SM_A1 + 16384)
#define SM_END   (SM_B1 + 16384)
#define GEMM_SMEM (SM_END + 1024)

__global__ void __launch_bounds__(256) gemm_tc_kernel(
    const float* __restrict__ bihf, const float* __restrict__ bhhf,
    const float* __restrict__ bihb, const float* __restrict__ bhhb)
{
    extern __shared__ char smem_raw[];
    uint32_t raw = smem_u32(smem_raw);
    uint32_t pad = (1024u - (raw & 1023u)) & 1023u;
    uint32_t sb = raw + pad;
    char* sm = smem_raw + pad;

    const int tid  = threadIdx.x;
    const int wid  = tid >> 5, lane = tid & 31;
    const int wm   = wid & 3;          // 0..3 -> m offset wm*32
    const int wn   = wid >> 2;         // 0..1 -> n offset wn*64
    const int dir  = blockIdx.z;
    const int m0   = blockIdx.x * 128;
    const int n0   = blockIdx.y * 128;

    const __nv_bfloat16* __restrict__ Wsrc = g_wb + (size_t)dir * G4 * DD;
    const float* __restrict__ bi = dir ? bihb : bihf;
    const float* __restrict__ bh = dir ? bhhb : bhhf;
    float* bias_s = (float*)(sm + SM_BIAS);

    if (tid < 128) bias_s[tid] = bi[n0 + tid] + bh[n0 + tid];

    const uint32_t Aoff[2] = { SM_A0, SM_A1 };
    const uint32_t Boff[2] = { SM_B0, SM_B1 };

    // chunk loader: 128 rows x 64 bf16 (128 B/row, SW128) for A and B via cp.async
    auto load_chunk = [&](int c) {
        const int buf = c & 1;
        const int kc  = c * 64;
        uint32_t Ab = sb + Aoff[buf];
        uint32_t Bb = sb + Boff[buf];
#pragma unroll
        for (int it = 0; it < 4; it++) {
            int idx = tid + it * 256;          // 0..1023
            int r  = idx >> 3;                 // row 0..127
            int cg = idx & 7;                  // 16B col group
            uint32_t swo = sw128((uint32_t)(r * 128 + cg * 16));
            const char* srcA = (const char*)g_xb + ((size_t)(m0 + r) * DD + kc + cg * 8) * 2;
            const char* srcB = (const char*)Wsrc + ((size_t)(n0 + r) * DD + kc + cg * 8) * 2;
            CP_ASYNC16(Ab + swo, srcA);
            CP_ASYNC16(Bb + swo, srcB);
        }
        CP_COMMIT();
    };

    float acc[2][8][4];
#pragma unroll
    for (int i = 0; i < 2; i++)
#pragma unroll
        for (int j = 0; j < 8; j++)
#pragma unroll
            for (int q = 0; q < 4; q++) acc[i][j][q] = 0.f;

    // precomputed ldmatrix lane address components
    const int a_row_base = wm * 32 + (lane & 15);        // + mf*16
    const int a_cb       = (lane >> 4) * 16;             // + kbyte
    const int b_row_base = wn * 64 + (lane & 7) + ((lane >> 4) << 3);   // + nf2*16
    const int b_cb       = ((lane >> 3) & 1) * 16;       // + kbyte

    load_chunk(0);
    load_chunk(1);

    for (int c = 0; c < 12; c++) {
        if (c < 11) { CP_WAIT(1); } else { CP_WAIT(0); }
        __syncthreads();
        const uint32_t Ab = sb + Aoff[c & 1];
        const uint32_t Bb = sb + Boff[c & 1];
#pragma unroll
        for (int ks = 0; ks < 4; ks++) {
            const int kbyte = ks * 32;
            uint32_t a[2][4];
#pragma unroll
            for (int mf = 0; mf < 2; mf++) {
                uint32_t off = (uint32_t)((a_row_base + mf * 16) * 128 + a_cb + kbyte);
                ldsm_x4(a[mf][0], a[mf][1], a[mf][2], a[mf][3], Ab + sw128(off));
            }
#pragma unroll
            for (int nf2 = 0; nf2 < 4; nf2++) {
                uint32_t b0, b1, b2, b3;
                uint32_t off = (uint32_t)((b_row_base + nf2 * 16) * 128 + b_cb + kbyte);
                ldsm_x4(b0, b1, b2, b3, Bb + sw128(off));
#pragma unroll
                for (int mf = 0; mf < 2; mf++) {
                    mma_16816(acc[mf][nf2 * 2 + 0], a[mf], b0, b1);
                    mma_16816(acc[mf][nf2 * 2 + 1], a[mf], b2, b3);
                }
            }
        }
        __syncthreads();
        if (c + 2 < 12) load_chunk(c + 2);
    }

    // epilogue: add bias, scatter to g_gx[dir][t][b][n]
    const int qq = lane & 3;
#pragma unroll
    for (int mf = 0; mf < 2; mf++) {
        const int rloc0 = wm * 32 + mf * 16 + (lane >> 2);
        const int row0  = m0 + rloc0;
        const int row1  = row0 + 8;
        const int b0i = row0 / TT, t0 = row0 % TT;
        const int b1i = row1 / TT, t1 = row1 % TT;
        float* dst0 = g_gx + (((size_t)dir * TT + t0) * BB + b0i) * G4 + n0;
        float* dst1 = g_gx + (((size_t)dir * TT + t1) * BB + b1i) * G4 + n0;
#pragma unroll
        for (int nf = 0; nf < 8; nf++) {
            const int cl = wn * 64 + nf * 8 + 2 * qq;
            float bx = bias_s[cl], by = bias_s[cl + 1];
            float2 v0 = { acc[mf][nf][0] + bx, acc[mf][nf][1] + by };
            float2 v1 = { acc[mf][nf][2] + bx, acc[mf][nf][3] + by };
            *(float2*)(dst0 + cl) = v0;
            *(float2*)(dst1 + cl) = v1;
        }
    }
}

// ---------------------------------------------------------------------------
// KD loss partials
// ---------------------------------------------------------------------------
__global__ void __launch_bounds__(256) kd_kernel(const float* __restrict__ s,
                                                 const float* __restrict__ t)
{
    __shared__ float red[256];
    const size_t N4 = (size_t)3 * BB * TT * DD / 4;
    const float4* s4 = (const float4*)s;
    const float4* t4 = (const float4*)t;
    float acc = 0.f;
    for (size_t i = (size_t)blockIdx.x * 256 + threadIdx.x; i < N4; i += 262144) {
        float4 a = __ldg(s4 + i);
        float4 b = __ldg(t4 + i);
        float dx = a.x - b.x, dy = a.y - b.y, dz = a.z - b.z, dw = a.w - b.w;
        acc += dx * dx + dy * dy + dz * dz + dw * dw;
    }
    red[threadIdx.x] = acc;
    __syncthreads();
    for (int o = 128; o; o >>= 1) {
        if (threadIdx.x < o) red[threadIdx.x] += red[threadIdx.x + o];
        __syncthreads();
    }
    if (threadIdx.x == 0) g_kdpart[blockIdx.x] = red[0];
}

// ---------------------------------------------------------------------------
// Persistent BiLSTM recurrence. 128 blocks = 2 dir x 32 hid-groups x 2 b-groups.
// 4 independent barrier groups (dir,bg) of 32 blocks; release/acquire barrier.
// ---------------------------------------------------------------------------
__device__ __forceinline__ float sigmoid_f(float x) { return 1.f / (1.f + __expf(-x)); }
__device__ __forceinline__ float tanh_f(float x) {
    x = fminf(15.f, fmaxf(-15.f, x));
    float e = __expf(2.f * x);
    return (e - 1.f) / (e + 1.f);
}

__global__ void __launch_bounds__(256, 1) recur_kernel(
    const float* __restrict__ Whhf, const float* __restrict__ Whhb)
{
    const int tid = threadIdx.x;
    const int w   = tid >> 5;
    const int rl  = tid & 31;
    const int blk = blockIdx.x;
    const int dir = blk >> 6;
    const int hg  = (blk & 63) >> 1;
    const int bg  = blk & 1;
    const int hidbase = hg * 8;
    const int bbase   = bg * 16;
    const int gidx    = dir * 2 + bg;            // barrier group (32 blocks)
    const int R = ((rl >> 3) << 8) + hidbase + (rl & 7);

    const float* __restrict__ Whh = dir ? Whhb : Whhf;

    u64 Wreg[16];
    {
        const float4* wp = (const float4*)(Whh + (size_t)R * HH + w * 32);
#pragma unroll
        for (int i = 0; i < 8; i++) {
            float4 v = wp[i];
            Wreg[2 * i]     = pack2(v.x, v.y);
            Wreg[2 * i + 1] = pack2(v.z, v.w);
        }
    }

    __shared__ __align__(16) float h_s[16 * HH];
    __shared__ float part_s[8 * 16 * 32];
    __shared__ float gate_s[16 * 32];

    float c_state = 0.f;
    const int bl = tid >> 3;
    const int jj = tid & 7;
    unsigned int* ctr = &g_barg[gidx * 32];

    for (int s = 0; s < TT; s++) {
        const int t = dir ? (TT - 1 - s) : s;

        // stage h (L2-coherent reads)
        {
            const float4* src = (const float4*)(g_hbuf +
                ((size_t)((s & 1) * 2 + dir) * BB + bbase) * HH);
            float4* dst4 = (float4*)h_s;
#pragma unroll
            for (int q = 0; q < 4; q++)
                dst4[tid + q * 256] = __ldcg(src + tid + q * 256);
        }
        __syncthreads();

        float gx0, gx1;
        {
            const float* gxp = g_gx + (((size_t)dir * TT + t) * BB + bbase) * G4;
            gx0 = __ldg(gxp + (size_t)w * G4 + R);
            gx1 = __ldg(gxp + (size_t)(8 + w) * G4 + R);
        }

#pragma unroll 4
        for (int b = 0; b < 16; b++) {
            const u64* h2 = (const u64*)(h_s + b * HH + w * 32);
            u64 acc = 0ull;
#pragma unroll
            for (int i = 0; i < 16; i++) fma2(acc, Wreg[i], h2[i]);
            float2 f = unpack2(acc);
            part_s[w * 512 + b * 32 + rl] = f.x + f.y;
        }
        __syncthreads();

        {
            float s0 = gx0, s1 = gx1;
#pragma unroll
            for (int q = 0; q < 8; q++) {
                s0 += part_s[q * 512 + w * 32 + rl];
                s1 += part_s[q * 512 + (8 + w) * 32 + rl];
            }
            gate_s[w * 32 + rl]       = s0;
            gate_s[(8 + w) * 32 + rl] = s1;
        }
        __syncthreads();

        if (tid < 128) {
            float gi = gate_s[bl * 32 + jj];
            float gf = gate_s[bl * 32 + 8 + jj];
            float gg = gate_s[bl * 32 + 16 + jj];
            float go = gate_s[bl * 32 + 24 + jj];
            float si = sigmoid_f(gi);
            float sf = sigmoid_f(gf);
            float so = sigmoid_f(go);
            c_state = sf * c_state + si * tanh_f(gg);
            float h = so * tanh_f(c_state);
            int bglob = bbase + bl;
            int hglob = hidbase + jj;
            __stcg(g_hbuf + ((size_t)(((s + 1) & 1) * 2 + dir) * BB + bglob) * HH + hglob, h);
            g_hs[(((size_t)dir * BB + bglob) * TT + t) * HH + hglob] = h;
        }
        __syncthreads();

        // group barrier: release arrival + acquire poll (32 blocks per group)
        if (tid == 0) {
            asm volatile("red.release.gpu.global.add.u32 [%0], %1;" :: "l"(ctr), "r"(1u) : "memory");
            unsigned target = 32u * (unsigned)(s + 1);
            unsigned v;
            do {
                asm volatile("ld.acquire.gpu.global.u32 %0, [%1];" : "=r"(v) : "l"(ctr) : "memory");
            } while (v < target);
        }
        __syncthreads();
    }
}

// ---------------------------------------------------------------------------
// Logits: one warp per (b,t) row
// ---------------------------------------------------------------------------
__global__ void __launch_bounds__(256) logits_kernel(
    const float* __restrict__ Wcls, const float* __restrict__ bcls)
{
    __shared__ __align__(16) float Ws[2 * 512];
    const int tid = threadIdx.x;
    for (int i = tid; i < 1024; i += 256) Ws[i] = Wcls[i];
    __syncthreads();

    const int warp = tid >> 5, lane = tid & 31;
    const int row = blockIdx.x * 8 + warp;
    const int b = row / TT, t = row % TT;

    const float4* hf  = (const float4*)(g_hs + ((size_t)b * TT + t) * HH);
    const float4* hb  = (const float4*)(g_hs + (((size_t)BB + b) * TT + t) * HH);
    const float4* W0  = (const float4*)Ws;
    const float4* W1  = (const float4*)(Ws + 512);

    float a0 = 0.f, a1 = 0.f;
#pragma unroll
    for (int q = 0; q < 2; q++) {
        int u = lane + q * 32;
        float4 v  = hf[u];
        float4 w0 = W0[u];
        float4 w1 = W1[u];
        a0 += v.x * w0.x + v.y * w0.y + v.z * w0.z + v.w * w0.w;
        a1 += v.x * w1.x + v.y * w1.y + v.z * w1.z + v.w * w1.w;
    }
#pragma unroll
    for (int q = 0; q < 2; q++) {
        int u = lane + q * 32;
        float4 v  = hb[u];
        float4 w0 = W0[64 + u];
        float4 w1 = W1[64 + u];
        a0 += v.x * w0.x + v.y * w0.y + v.z * w0.z + v.w * w0.w;
        a1 += v.x * w1.x + v.y * w1.y + v.z * w1.z + v.w * w1.w;
    }
#pragma unroll
    for (int o = 16; o; o >>= 1) {
        a0 += __shfl_down_sync(0xffffffffu, a0, o);
        a1 += __shfl_down_sync(0xffffffffu, a1, o);
    }
    if (lane == 0) {
        g_logits[row * 2]     = a0 + bcls[0];
        g_logits[row * 2 + 1] = a1 + bcls[1];
    }
}

// ---------------------------------------------------------------------------
// CRF forward + numerator + final loss
// ---------------------------------------------------------------------------
__device__ __forceinline__ float lse2(float a, float b) {
    float m = fmaxf(a, b);
    return m + log1pf(__expf(-fabsf(a - b)));
}

__global__ void crf_kernel(const float* __restrict__ cst,
                           const float* __restrict__ cen,
                           const float* __restrict__ ctr,
                           const int* __restrict__ labels,
                           const int* __restrict__ mask,
                           float* __restrict__ out)
{
    const int b = threadIdx.x;
    const float tr00 = ctr[0], tr01 = ctr[1], tr10 = ctr[2], tr11 = ctr[3];
    const float* em = g_logits + (size_t)b * TT * 2;
    const int* lab = labels + (size_t)b * TT;
    const int* msk = mask   + (size_t)b * TT;

    float e0 = em[0], e1 = em[1];
    float a0 = cst[0] + e0, a1 = cst[1] + e1;

    int tag_prev = lab[0]; if (tag_prev == -100) tag_prev = 0;
    float num = cst[tag_prev] + (tag_prev ? e1 : e0);
    int cnt = 1;

    for (int t = 1; t < TT; t++) {
        int mraw = msk[t];
        float mt = (mraw != 0) ? 1.f : 0.f;
        float em0 = em[t * 2], em1 = em[t * 2 + 1];
        int tag = lab[t]; if (tag == -100) tag = 0;

        float trs = tag ? (tag_prev ? tr11 : tr01) : (tag_prev ? tr10 : tr00);
        float ems = tag ? em1 : em0;
        num += mt * (trs + ems);
        tag_prev = tag;
        cnt += (mraw != 0);

        float n0 = em0 + lse2(a0 + tr00, a1 + tr10);
        float n1 = em1 + lse2(a0 + tr01, a1 + tr11);
        if (mraw != 0) { a0 = n0; a1 = n1; }
    }
    int lt = lab[cnt - 1]; if (lt == -100) lt = 0;
    num += cen[lt];

    float logZ = lse2(a0 + cen[0], a1 + cen[1]);
    float v = num - logZ;

    float kdp = 0.f;
#pragma unroll
    for (int i = 0; i < 32; i++) kdp += g_kdpart[b * 32 + i];

#pragma unroll
    for (int o = 16; o; o >>= 1) {
        v   += __shfl_down_sync(0xffffffffu, v, o);
        kdp += __shfl_down_sync(0xffffffffu, kdp, o);
    }
    if (b == 0) {
        float span = -v / (float)BB;
        float kd = kdp / ((float)3 * BB * TT * DD);
        out[0] = 0.5f * span + 0.5f * kd;
    }
}

// ---------------------------------------------------------------------------
// Launch
// ---------------------------------------------------------------------------
extern "C" void kernel_launch(void* const* d_in, const int* in_sizes, int n_in,
                              void* d_out, int out_size)
{
    const float* top  = (const float*)d_in[0];
    const float* sfe  = (const float*)d_in[1];
    const float* tfe  = (const float*)d_in[2];
    const float* Wihf = (const float*)d_in[3];
    const float* Whhf = (const float*)d_in[4];
    const float* bihf = (const float*)d_in[5];
    const float* bhhf = (const float*)d_in[6];
    const float* Wihb = (const float*)d_in[7];
    const float* Whhb = (const float*)d_in[8];
    const float* bihb = (const float*)d_in[9];
    const float* bhhb = (const float*)d_in[10];
    const float* Wcls = (const float*)d_in[11];
    const float* bcls = (const float*)d_in[12];
    const float* cst  = (const float*)d_in[13];
    const float* cen  = (const float*)d_in[14];
    const float* ctr  = (const float*)d_in[15];
    const int*   lab  = (const int*)d_in[16];
    const int*   msk  = (const int*)d_in[17];
    float* out = (float*)d_out;

    cudaFuncSetAttribute(gemm_tc_kernel, cudaFuncAttributeMaxDynamicSharedMemorySize, GEMM_SMEM);

    init_kernel<<<1, 256>>>();

    cvt_kernel<<<2048, 256>>>(top, Wihf, Wihb);

    dim3 gg(14336 / 128, G4 / 128, 2);               // 112 x 8 x 2
    gemm_tc_kernel<<<gg, 256, GEMM_SMEM>>>(bihf, bhhf, bihb, bhhb);

    kd_kernel<<<1024, 256>>>(sfe, tfe);

    recur_kernel<<<128, 256>>>(Whhf, Whhb);

    logits_kernel<<<(BB * TT) / 8, 256>>>(Wcls, bcls);

    crf_kernel<<<1, 32>>>(cst, cen, ctr, lab, msk, out);
}